// round 17
// baseline (speedup 1.0000x reference)
#include <cuda_runtime.h>
#include <cuda_fp16.h>
#include <cstdint>
#include <math.h>

// Problem dims (SimpleLSTM): B=64, T=512, D=1024, H=1024
#define B_  64
#define T_  512
#define D_  1024
#define H_  1024
#define G4_ 4096   // 4*H

// ---------------- scratch (device globals: allocation-free) ----------------
__device__ float g_xproj[(size_t)T_ * B_ * G4_];      // [T*B][4H] fp32 (m = t*64+b)
// xs in fp16 A-frag (m16n8k16) layout: uint4 idx ((strip*64 + ki)*32 + lane)
__device__ __half g_xsA_h[(size_t)2048 * 64 * 32 * 8];   // 64MB
// Wx in fp16 B-frag pair layout: uint4 idx ((ng2*64 + ki)*32 + lane)
__device__ __half g_WxB_h[(size_t)256 * 64 * 32 * 8];    // 8MB
// hidden state fp16 A-frag: uint4 idx ((ki*4 + strip)*32 + lane). Double buf.
__device__ __half g_hperm_h[2][B_ * H_];

// barrier state
struct PadCnt { unsigned v; unsigned pad[31]; };   // 128B spacing
__device__ PadCnt g_cnt1[8];     // initial barrier: [g*4 + sub]
__device__ PadCnt g_cnt2g[2];
__device__ PadCnt g_geng[2];
// per-BLOCK monotonic step gens (producer side of the h handoff)
__device__ PadCnt g_bgen[128];

// ---------------- helpers ----------------
__device__ __forceinline__ void cp_async16(void* dst, const void* src) {
    uint32_t s = (uint32_t)__cvta_generic_to_shared(dst);
    asm volatile("cp.async.cg.shared.global [%0], [%1], 16;\n" :: "r"(s), "l"(src));
}
__device__ __forceinline__ void cp_commit() { asm volatile("cp.async.commit_group;\n"); }
template<int N>
__device__ __forceinline__ void cp_wait() { asm volatile("cp.async.wait_group %0;\n" :: "n"(N)); }

__device__ __forceinline__ void mma_f16(float4& d, const uint4& a,
                                        unsigned b0, unsigned b1) {
    asm volatile(
        "mma.sync.aligned.m16n8k16.row.col.f32.f16.f16.f32 "
        "{%0,%1,%2,%3}, {%4,%5,%6,%7}, {%8,%9}, {%0,%1,%2,%3};"
        : "+f"(d.x), "+f"(d.y), "+f"(d.z), "+f"(d.w)
        : "r"(a.x), "r"(a.y), "r"(a.z), "r"(a.w), "r"(b0), "r"(b1));
}
__device__ __forceinline__ float sigmoid_f(float x) {
    return __fdividef(1.0f, 1.0f + __expf(-x));
}
__device__ __forceinline__ float tanh_f(float x) {
    return __fdividef(2.0f, 1.0f + __expf(-2.0f * x)) - 1.0f;
}
__device__ __forceinline__ unsigned pack_h2(float lo, float hi) {
    __half2 h2 = __floats2half2_rn(lo, hi);
    return *reinterpret_cast<unsigned*>(&h2);
}
__device__ __forceinline__ unsigned ld_acq(const unsigned* p) {
    unsigned v;
    asm volatile("ld.acquire.gpu.global.u32 %0, [%1];" : "=r"(v) : "l"(p) : "memory");
    return v;
}
__device__ __forceinline__ void st_rel(unsigned* p, unsigned v) {
    asm volatile("st.release.gpu.global.u32 [%0], %1;" :: "l"(p), "r"(v) : "memory");
}

// group-local initial barrier (R15-proven)
__device__ __forceinline__ void bar_arrive_grp(int g, int bg) {
    __threadfence();
    unsigned o = atomicAdd(&g_cnt1[g * 4 + (bg >> 4)].v, 1u);
    if (o == 15u) {
        unsigned o2 = atomicAdd(&g_cnt2g[g].v, 1u);
        if (o2 == 3u) {
            #pragma unroll
            for (int i = 0; i < 4; i++) atomicExch(&g_cnt1[g * 4 + i].v, 0u);
            atomicExch(&g_cnt2g[g].v, 0u);
            __threadfence();
            atomicAdd(&g_geng[g].v, 1u);
        }
    }
}

// ============================================================================
// P1: permute xs -> g_xsA_h (fp16 A-frag layout).  (round-12, proven)
// ============================================================================
__global__ void __launch_bounds__(256) permA_kernel(const float* __restrict__ xs) {
    size_t x = (size_t)blockIdx.x * 256 + threadIdx.x;   // < 4,194,304
    int lane  = (int)(x & 31);
    int ki    = (int)((x >> 5) & 63);
    int strip = (int)(x >> 11);
    int r  = strip * 16 + (lane >> 2);
    int k  = ki * 16 + (lane & 3) * 2;
    auto ld2 = [&](int m, int kk) -> unsigned {
        int b = m & 63, t = m >> 6;
        const float* p = xs + ((size_t)b * T_ + t) * D_ + kk;
        return pack_h2(p[0], p[1]);
    };
    uint4 v;
    v.x = ld2(r,     k);
    v.y = ld2(r + 8, k);
    v.z = ld2(r,     k + 8);
    v.w = ld2(r + 8, k + 8);
    reinterpret_cast<uint4*>(g_xsA_h)[x] = v;
}

// ============================================================================
// P2: permute Wx -> g_WxB_h (fp16 B-frag pair layout).  (round-12, proven)
// ============================================================================
__global__ void __launch_bounds__(256) permB_kernel(const float* __restrict__ Wx) {
    size_t y = (size_t)blockIdx.x * 256 + threadIdx.x;   // < 524,288
    int lane = (int)(y & 31);
    int ki   = (int)((y >> 5) & 63);
    int ng2  = (int)(y >> 11);
    int tk = (lane & 3) * 2;
    int n  = lane >> 2;
    int kb = ki * 16;
    unsigned wd[4];
    #pragma unroll
    for (int w = 0; w < 4; w++) {
        int ng   = ng2 * 2 + (w >> 1);
        int krow = kb + tk + 8 * (w & 1);
        const float* colp = Wx + (size_t)ng * 8 + n;
        wd[w] = pack_h2(__ldg(colp + (size_t)krow * G4_),
                        __ldg(colp + (size_t)(krow + 1) * G4_));
    }
    reinterpret_cast<uint4*>(g_WxB_h)[y] = make_uint4(wd[0], wd[1], wd[2], wd[3]);
}

// ============================================================================
// Kernel G: xproj = xsA_h @ WxB_h  (round-14 version, proven, byte-identical)
// ============================================================================
__global__ void __launch_bounds__(256) xproj_kernel() {
    extern __shared__ uint4 smG[];   // 3 stages x 3072 uint4 = 147,456 B
    const int tid  = threadIdx.x;
    const int lane = tid & 31;
    const int w    = tid >> 5;
    const int wm   = w >> 1;
    const int wn   = w & 1;
    const int mt   = blockIdx.y;
    const int nt   = blockIdx.x;

    const uint4* xsA = reinterpret_cast<const uint4*>(g_xsA_h);
    const uint4* WxB = reinterpret_cast<const uint4*>(g_WxB_h);

    auto issue = [&](int ch) {
        uint4* stA = smG + (ch % 3) * 3072;
        uint4* stB = stA + 2048;
        #pragma unroll
        for (int it = 0; it < 8; it++) {
            int lin = tid + it * 256;
            int ln  = lin & 31;
            int dki = (lin >> 5) & 3;
            int st  = lin >> 7;
            cp_async16(&stA[(st * 4 + dki) * 32 + ln],
                       &xsA[((size_t)(mt * 16 + st) * 64 + ch * 4 + dki) * 32 + ln]);
        }
        #pragma unroll
        for (int it = 0; it < 4; it++) {
            int lin = tid + it * 256;
            int ln  = lin & 31;
            int dki = (lin >> 5) & 3;
            int lg  = lin >> 7;
            cp_async16(&stB[(lg * 4 + dki) * 32 + ln],
                       &WxB[((size_t)(nt * 8 + lg) * 64 + ch * 4 + dki) * 32 + ln]);
        }
    };

    float4 acc[4][8];
    #pragma unroll
    for (int s = 0; s < 4; s++)
        #pragma unroll
        for (int o = 0; o < 8; o++)
            acc[s][o] = make_float4(0.f, 0.f, 0.f, 0.f);

    issue(0); cp_commit();
    issue(1); cp_commit();

    #pragma unroll 1
    for (int ch = 0; ch < 16; ch++) {
        __syncthreads();
        if (ch + 2 < 16) { issue(ch + 2); cp_commit(); }
        if (ch < 14) cp_wait<2>(); else if (ch == 14) cp_wait<1>(); else cp_wait<0>();
        __syncthreads();

        const uint4* stA = smG + (ch % 3) * 3072;
        const uint4* stB = stA + 2048;
        #pragma unroll
        for (int d = 0; d < 4; d++) {
            uint4 a[4];
            #pragma unroll
            for (int s = 0; s < 4; s++)
                a[s] = stA[((wm * 4 + s) * 4 + d) * 32 + lane];
            #pragma unroll
            for (int p = 0; p < 4; p++) {
                uint4 wv = stB[((wn * 4 + p) * 4 + d) * 32 + lane];
                #pragma unroll
                for (int s = 0; s < 4; s++) {
                    mma_f16(acc[s][2 * p],     a[s], wv.x, wv.y);
                    mma_f16(acc[s][2 * p + 1], a[s], wv.z, wv.w);
                }
            }
        }
    }

    int r  = lane >> 2;
    int c2 = (lane & 3) * 2;
    #pragma unroll
    for (int s = 0; s < 4; s++)
        #pragma unroll
        for (int o = 0; o < 8; o++) {
            size_t row = (size_t)mt * 256 + (wm * 4 + s) * 16 + r;
            size_t col = (size_t)nt * 128 + (wn * 8 + o) * 8 + c2;
            *reinterpret_cast<float2*>(g_xproj + row * G4_ + col) =
                make_float2(acc[s][o].x, acc[s][o].y);
            *reinterpret_cast<float2*>(g_xproj + (row + 8) * G4_ + col) =
                make_float2(acc[s][o].z, acc[s][o].w);
        }
}

// ============================================================================
// Kernel B: persistent LSTM scan, 128 blocks x 128 thr (4 warps), fp16.
//   Two independent batch groups (R15). NEW vs R16: per-BLOCK producer gens
//   with per-CHUNK waits. Warp kq's chunk ci needs exactly blocks
//   g*64 + kq*16 + 2ci, +1 (block bg owns hperm ki == bg); it polls those
//   two gens (ld.acquire.gpu) right before issuing the chunk. A block
//   publishes its step with one st.release.gpu after writing its h slice.
//   Straggler waits overlap the GEMM pipeline instead of gating step start.
//   WAR-safe by the R16 induction (all warps collectively check all 64 gens
//   >= t before the sg syncthreads that precedes the hnext write).
// ============================================================================
__global__ void __launch_bounds__(128, 1) lstm_scan_kernel(
    const float* __restrict__ c0, const float* __restrict__ h0,
    const float* __restrict__ Wh, const float* __restrict__ bias,
    float* __restrict__ out)
{
    extern __shared__ float sm[];
    uint4* Whs4 = reinterpret_cast<uint4*>(sm);            // 8192 uint4 = 128KB
    uint4* hs4  = reinterpret_cast<uint4*>(sm) + 8192;     // 2048 uint4 = 32KB
    float* sg   = sm + 32768 + 8192;                       // 8448 floats = 33KB

    const int tid  = threadIdx.x;
    const int lane = tid & 31;
    const int kq   = tid >> 5;           // warp id == k-quarter (256 k)
    const int bIdx = blockIdx.x;
    const int g    = bIdx >> 6;          // batch group 0..1
    const int bg   = bIdx & 63;          // block-in-group == owned hperm ki
    const int j0   = bg * 16;
    const int gb   = g * 64 + kq * 16;   // base producer block for my k-quarter

    // ---- build Whs (fp16 B-frag pairs, 64 gate-cols; R13/R15-verified)
    for (int i = tid; i < 8192; i += 128) {
        int ln  = i & 31;
        int p   = (i >> 5) & 3;
        int ki2 = (i >> 7) & 15;
        int kqq = i >> 11;
        int tk = (ln & 3) * 2;
        int nn = ln >> 2;
        int kb = kqq * 256 + ki2 * 16;
        unsigned wd[4];
        #pragma unroll
        for (int ww = 0; ww < 4; ww++) {
            int c    = (p * 2 + (ww >> 1)) * 8 + nn;   // 0..63
            int gate = c >> 4, hcol = c & 15;
            int krow = kb + tk + 8 * (ww & 1);
            const float* colp = Wh + (size_t)gate * H_ + j0 + hcol;
            wd[ww] = pack_h2(__ldg(colp + (size_t)krow * G4_),
                             __ldg(colp + (size_t)(krow + 1) * G4_));
        }
        Whs4[i] = make_uint4(wd[0], wd[1], wd[2], wd[3]);
    }

    // ---- per-thread ownership: col j = j0 + (tid&15); local rows rowb + 8q
    const int rowb = tid >> 4;           // 0..7
    const int jj   = tid & 15;
    const int j    = j0 + jj;
    int bq[4];                           // GLOBAL batch rows
    #pragma unroll
    for (int q = 0; q < 4; q++) bq[q] = g * 32 + rowb + 8 * q;

    float creg[4], bia[4];
    #pragma unroll
    for (int gg = 0; gg < 4; gg++) bia[gg] = __ldg(bias + gg * H_ + j);
    #pragma unroll
    for (int q = 0; q < 4; q++) creg[q] = __ldg(c0 + (size_t)bq[q] * H_ + j);

    // ---- h write coords (fp16 A-frag; ki == bg; strip = global row>>4)
    int strip_w[4], lane_w[4], v_w[4];
    const int hi_w = jj & 1;
    #pragma unroll
    for (int q = 0; q < 4; q++) {
        int lr  = rowb + 8 * q;          // local row 0..31
        int r16 = lr & 15;
        strip_w[q] = g * 2 + (lr >> 4);
        lane_w[q]  = (r16 & 7) * 4 + ((jj & 7) >> 1);
        v_w[q]     = ((jj >> 3) << 1) | (r16 >> 3);
    }

    // ---- init g_hperm_h[0] = fp16(h0)
    #pragma unroll
    for (int q = 0; q < 4; q++) {
        size_t hidx = ((((size_t)bg * 4 + strip_w[q]) * 32 + lane_w[q]) * 4 + v_w[q]) * 2 + hi_w;
        g_hperm_h[0][hidx] = __float2half_rn(__ldg(h0 + (size_t)bq[q] * H_ + j));
    }

    // ---- xproj prefetch
    float xpr[4][4];
    auto prefetch_xp = [&](int t) {
        const float* xp = g_xproj + (size_t)t * B_ * G4_;
        #pragma unroll
        for (int q = 0; q < 4; q++)
            #pragma unroll
            for (int gg = 0; gg < 4; gg++)
                xpr[q][gg] = __ldg(xp + (size_t)bq[q] * G4_ + gg * H_ + j);
    };
    prefetch_xp(0);

    // ---- reset own per-block gen (before initial barrier)
    if (tid == 0) atomicExch(&g_bgen[bIdx].v, 0u);

    // ---- initial group sync (h0 + Whs + gen resets visible)
    __syncthreads();
    {
        if (tid == 0) {
            volatile unsigned* genp = &g_geng[g].v;
            unsigned mygen = *genp;
            bar_arrive_grp(g, bg);
            while (*genp == mygen) { }
            __threadfence();
        }
        __syncthreads();
    }

    for (int t = 0; t < T_; t++) {
        const uint4* hc4 = reinterpret_cast<const uint4*>(g_hperm_h[t & 1]);
        __half* hnext    = g_hperm_h[(t + 1) & 1];
        const unsigned tt = (unsigned)t;

        // wait for the two producer blocks of chunk ci, then issue it
        auto wait2 = [&](int ci) {
            while (ld_acq(&g_bgen[gb + 2 * ci].v)     < tt) { }
            while (ld_acq(&g_bgen[gb + 2 * ci + 1].v) < tt) { }
        };
        auto issue = [&](int ci) {
            uint4* dst = hs4 + kq * 512 + (ci & 3) * 128;
            #pragma unroll
            for (int it = 0; it < 4; it++) {
                int dki = it >> 1;
                int sL  = it & 1;
                int ki  = kq * 16 + ci * 2 + dki;
                cp_async16(&dst[(dki * 2 + sL) * 32 + lane],
                           &hc4[((size_t)ki * 4 + (g * 2 + sL)) * 32 + lane]);
            }
        };

        wait2(0); issue(0); cp_commit();
        wait2(1); issue(1); cp_commit();
        wait2(2); issue(2); cp_commit();
        wait2(3); issue(3); cp_commit();

        float4 acc[2][8];   // [local strip][octet]
        #pragma unroll
        for (int s = 0; s < 2; s++)
            #pragma unroll
            for (int o = 0; o < 8; o++)
                acc[s][o] = make_float4(0.f, 0.f, 0.f, 0.f);

        #pragma unroll 4
        for (int ch = 0; ch < 8; ch++) {
            if (ch < 5)       cp_wait<3>();
            else if (ch == 5) cp_wait<2>();
            else if (ch == 6) cp_wait<1>();
            else              cp_wait<0>();

            const uint4* st = hs4 + kq * 512 + (ch & 3) * 128;
            #pragma unroll
            for (int d = 0; d < 2; d++) {
                int ki2 = ch * 2 + d;
                uint4 a0 = st[(d * 2 + 0) * 32 + lane];
                uint4 a1 = st[(d * 2 + 1) * 32 + lane];
                #pragma unroll
                for (int p = 0; p < 4; p++) {
                    uint4 wv = Whs4[((kq * 16 + ki2) * 4 + p) * 32 + lane];
                    mma_f16(acc[0][2 * p],     a0, wv.x, wv.y);
                    mma_f16(acc[0][2 * p + 1], a0, wv.z, wv.w);
                    mma_f16(acc[1][2 * p],     a1, wv.x, wv.y);
                    mma_f16(acc[1][2 * p + 1], a1, wv.z, wv.w);
                }
            }
            if (ch + 4 < 8) { wait2(ch + 4); issue(ch + 4); cp_commit(); }
        }

        // ---- stage partials: sg[kq][local row (stride 66)][col = o*8 + c2]
        {
            int r  = lane >> 2;
            int c2 = (lane & 3) * 2;
            float* base = sg + (size_t)kq * 32 * 66;
            #pragma unroll
            for (int s = 0; s < 2; s++)
                #pragma unroll
                for (int o = 0; o < 8; o++) {
                    int row0 = s * 16 + r;
                    *reinterpret_cast<float2*>(base + row0 * 66 + o * 8 + c2) =
                        make_float2(acc[s][o].x, acc[s][o].y);
                    *reinterpret_cast<float2*>(base + (row0 + 8) * 66 + o * 8 + c2) =
                        make_float2(acc[s][o].z, acc[s][o].w);
                }
        }
        __syncthreads();

        // ---- reduce 4 k-quarters + fused elementwise (flax order i,f,g,o)
        float hnv[4];
        #pragma unroll
        for (int q = 0; q < 4; q++) {
            int lr = rowb + 8 * q;
            float gv[4];
            #pragma unroll
            for (int gg = 0; gg < 4; gg++) {
                float sum = 0.f;
                #pragma unroll
                for (int kk = 0; kk < 4; kk++)
                    sum += sg[(size_t)kk * 32 * 66 + lr * 66 + gg * 16 + jj];
                gv[gg] = sum;
            }
            float pi = gv[0] + xpr[q][0] + bia[0];
            float pf = gv[1] + xpr[q][1] + bia[1];
            float pg = gv[2] + xpr[q][2] + bia[2];
            float po = gv[3] + xpr[q][3] + bia[3];
            float cn = sigmoid_f(pf) * creg[q] + sigmoid_f(pi) * tanh_f(pg);
            float hn = sigmoid_f(po) * tanh_f(cn);
            creg[q] = cn;
            hnv[q] = hn;
        }

        // ---- write hnext (fp16, permuted)
        #pragma unroll
        for (int q = 0; q < 4; q++) {
            size_t hidx = ((((size_t)bg * 4 + strip_w[q]) * 32 + lane_w[q]) * 4 + v_w[q]) * 2 + hi_w;
            hnext[hidx] = __float2half_rn(hnv[q]);
        }

        // ---- publish own gen (release: hnext writes of ALL warps ordered by
        //      the syncthreads above + release store by tid 0)
        __syncthreads();
        if (tid == 0) st_rel(&g_bgen[bIdx].v, tt + 1u);

        // ---- post-publish work: ys stores, hT, next xproj prefetch
        #pragma unroll
        for (int q = 0; q < 4; q++)
            out[2 * B_ * H_ + ((size_t)bq[q] * T_ + t) * H_ + j] = hnv[q];
        if (t == T_ - 1) {
            #pragma unroll
            for (int q = 0; q < 4; q++)
                out[B_ * H_ + (size_t)bq[q] * H_ + j] = hnv[q];
        }
        if (t + 1 < T_) prefetch_xp(t + 1);
    }

    // cT
    #pragma unroll
    for (int q = 0; q < 4; q++)
        out[(size_t)bq[q] * H_ + j] = creg[q];
}

// ============================================================================
// Launch. Inputs: c0, h0, xs, Wx, Wh, b. Output fp32: [cT][hT][ys]
// ============================================================================
extern "C" void kernel_launch(void* const* d_in, const int* in_sizes, int n_in,
                              void* d_out, int out_size) {
    const float* c0   = (const float*)d_in[0];
    const float* h0   = (const float*)d_in[1];
    const float* xs   = (const float*)d_in[2];
    const float* Wx   = (const float*)d_in[3];
    const float* Wh   = (const float*)d_in[4];
    const float* bias = (const float*)d_in[5];
    float* out = (float*)d_out;

    constexpr int G_SMEM    = 3 * 3072 * 16;                  // 147,456 B
    constexpr int SCAN_SMEM = (32768 + 8192 + 8448) * 4;      // 197,632 B
    cudaFuncSetAttribute(xproj_kernel,
                         cudaFuncAttributeMaxDynamicSharedMemorySize, G_SMEM);
    cudaFuncSetAttribute(lstm_scan_kernel,
                         cudaFuncAttributeMaxDynamicSharedMemorySize, SCAN_SMEM);

    permA_kernel<<<16384, 256>>>(xs);     // 4,194,304 uint4 / 256
    permB_kernel<<<2048, 256>>>(Wx);      // 524,288 uint4 / 256
    dim3 gridG(32, 128);                  // nt x mt (BM=256)
    xproj_kernel<<<gridG, 256, G_SMEM>>>();
    lstm_scan_kernel<<<128, 128, SCAN_SMEM>>>(c0, h0, Wh, bias, out);
}